// round 1
// baseline (speedup 1.0000x reference)
#include <cuda_runtime.h>
#include <cstdint>

typedef unsigned long long ull;

#define B_   4
#define S_   2048
#define DM_  2048
#define DS_  64
#define REC_ 512   // floats per (b,t) record in g_inp

// ---------------- f32x2 packed helpers (Blackwell) ----------------
__device__ __forceinline__ ull fma2(ull a, ull b, ull c) {
    ull d; asm("fma.rn.f32x2 %0,%1,%2,%3;" : "=l"(d) : "l"(a), "l"(b), "l"(c)); return d;
}
__device__ __forceinline__ ull mul2(ull a, ull b) {
    ull d; asm("mul.rn.f32x2 %0,%1,%2;" : "=l"(d) : "l"(a), "l"(b)); return d;
}
__device__ __forceinline__ ull pack2(float lo, float hi) {
    ull d; asm("mov.b64 %0, {%1,%2};" : "=l"(d) : "f"(lo), "f"(hi)); return d;
}
__device__ __forceinline__ float2 unpack2(ull a) {
    float lo, hi; asm("mov.b64 {%0,%1}, %2;" : "=f"(lo), "=f"(hi) : "l"(a));
    return make_float2(lo, hi);
}

// ---------------- cp.async helpers ----------------
__device__ __forceinline__ void cp_async8(void* smem, const void* gmem) {
    uint32_t s = (uint32_t)__cvta_generic_to_shared(smem);
    asm volatile("cp.async.ca.shared.global [%0], [%1], 8;" :: "r"(s), "l"(gmem) : "memory");
}
#define CP_COMMIT()  asm volatile("cp.async.commit_group;" ::: "memory")
#define CP_WAIT2()   asm volatile("cp.async.wait_group 2;" ::: "memory")

// ---------------- scratch (device globals: no runtime alloc) ----------------
__device__ float g_raw[B_ * S_ * 256];   // [m][256]: k(0:64) v(64:128) q(128:192) r_pre(192:256)
__device__ float g_inp[B_ * S_ * REC_];  // [m][512]: q k a km qa v c
__device__ float g_y  [B_ * S_ * DS_];   // scan output y

// =====================================================================
// Kernel A: projection GEMM.  out[m][nt*64+n] = sum_k x[m][k]*W_nt[n][k]
// Tiles: BM=64 x BN=64 x BK=16, 256 threads, 4x4 thread tile, f32x2 packed.
// =====================================================================
#define BM 64
#define BN 64
#define BK 16

__global__ void __launch_bounds__(256) proj_gemm(
    const float* __restrict__ x,
    const float* __restrict__ Wk, const float* __restrict__ Wv,
    const float* __restrict__ Wq, const float* __restrict__ Wa)
{
    __shared__ __align__(16) float As[BK][BM + 2];
    __shared__ __align__(16) float Bs[BK][BN + 2];

    const int mt = blockIdx.x;          // 0..127
    const int nt = blockIdx.y;          // 0..3 selects weight matrix
    const float* W = (nt == 0) ? Wk : (nt == 1) ? Wv : (nt == 2) ? Wq : Wa;

    const int tid  = threadIdx.x;
    const int lrow = tid >> 2;          // 0..63
    const int lk   = (tid & 3) * 4;     // 0,4,8,12
    const float* xg = x + (size_t)(mt * BM + lrow) * DM_ + lk;
    const float* wg = W + (size_t)lrow * DM_ + lk;

    const int tn4 = (tid & 15) * 4;     // col base 0..60
    const int tm4 = (tid >> 4) * 4;     // row base 0..60

    ull acc[4][2];
    #pragma unroll
    for (int i = 0; i < 4; i++) { acc[i][0] = 0ull; acc[i][1] = 0ull; }

    float4 av = *(const float4*)xg;
    float4 bv = *(const float4*)wg;

    for (int k0 = 0; k0 < DM_; k0 += BK) {
        __syncthreads();
        As[lk + 0][lrow] = av.x; As[lk + 1][lrow] = av.y;
        As[lk + 2][lrow] = av.z; As[lk + 3][lrow] = av.w;
        Bs[lk + 0][lrow] = bv.x; Bs[lk + 1][lrow] = bv.y;
        Bs[lk + 2][lrow] = bv.z; Bs[lk + 3][lrow] = bv.w;
        float4 avn = av, bvn = bv;
        if (k0 + BK < DM_) {
            avn = *(const float4*)(xg + k0 + BK);
            bvn = *(const float4*)(wg + k0 + BK);
        }
        __syncthreads();
        #pragma unroll
        for (int kk = 0; kk < BK; kk++) {
            ull b0 = *(const ull*)&Bs[kk][tn4];
            ull b1 = *(const ull*)&Bs[kk][tn4 + 2];
            #pragma unroll
            for (int i = 0; i < 4; i++) {
                float a = As[kk][tm4 + i];
                ull pa = pack2(a, a);
                acc[i][0] = fma2(pa, b0, acc[i][0]);
                acc[i][1] = fma2(pa, b1, acc[i][1]);
            }
        }
        av = avn; bv = bvn;
    }

    #pragma unroll
    for (int i = 0; i < 4; i++) {
        int m = mt * BM + tm4 + i;
        #pragma unroll
        for (int j = 0; j < 2; j++) {
            float2 f = unpack2(acc[i][j]);
            *(float2*)&g_raw[(size_t)m * 256 + nt * 64 + tn4 + 2 * j] = f;
        }
    }
}

// =====================================================================
// Kernel B: per-(b,t) prep. One warp per token. Lane handles d and d+32.
// Outputs record: [0]q [64]k [128]a [192]km=k*(1-a) [256]qa=q*a [320]v [384]c
// =====================================================================
__global__ void __launch_bounds__(256) prep_kernel(
    const float* __restrict__ Wa_b, const float* __restrict__ lam)
{
    const int g    = blockIdx.x * 8 + (threadIdx.x >> 5);   // token id 0..8191
    const int lane = threadIdx.x & 31;
    const float* r_ = g_raw + (size_t)g * 256;

    float k0 = r_[lane],        k1 = r_[lane + 32];
    float v0 = r_[64 + lane],   v1 = r_[96 + lane];
    float q0 = r_[128 + lane],  q1 = r_[160 + lane];
    float z0 = r_[192 + lane] + Wa_b[lane];
    float z1 = r_[224 + lane] + Wa_b[lane + 32];

    float kn = k0 * k0 + k1 * k1;
    #pragma unroll
    for (int m = 1; m < 32; m <<= 1) kn += __shfl_xor_sync(~0u, kn, m);
    float kinv = 1.0f / fmaxf(sqrtf(kn), 1e-12f);
    k0 *= kinv; k1 *= kinv;

    float qn = q0 * q0 + q1 * q1;
    #pragma unroll
    for (int m = 1; m < 32; m <<= 1) qn += __shfl_xor_sync(~0u, qn, m);
    float qinv = 1.0f / fmaxf(sqrtf(qn), 1e-12f);
    q0 *= qinv; q1 *= qinv;

    float la0 = logf(1.0f / (1.0f + expf(-lam[lane])) + 1e-8f);
    float la1 = logf(1.0f / (1.0f + expf(-lam[lane + 32])) + 1e-8f);
    float rr0 = 1.0f / (1.0f + expf(-z0));
    float rr1 = 1.0f / (1.0f + expf(-z1));
    float al0 = expf(8.0f * rr0 * la0);
    float al1 = expf(8.0f * rr1 * la1);
    float km0 = k0 * (1.0f - al0), km1 = k1 * (1.0f - al1);
    float qa0 = q0 * al0,          qa1 = q1 * al1;

    float c = q0 * km0 + q1 * km1;
    #pragma unroll
    for (int m = 1; m < 32; m <<= 1) c += __shfl_xor_sync(~0u, c, m);

    float* o = g_inp + (size_t)g * REC_;
    o[lane] = q0;        o[lane + 32] = q1;
    o[64 + lane] = k0;   o[96 + lane] = k1;
    o[128 + lane] = al0; o[160 + lane] = al1;
    o[192 + lane] = km0; o[224 + lane] = km1;
    o[256 + lane] = qa0; o[288 + lane] = qa1;
    o[320 + lane] = v0;  o[352 + lane] = v1;
    if (lane == 0) o[384] = c;
}

// =====================================================================
// Kernel C: sequential scan. 4 CTAs (one per batch), 256 threads.
// Thread (v = tid>>2, kg = tid&3) owns H[kg*16 .. kg*16+15][v] as 8 f32x2.
// cp.async 4-stage input pipeline, one __syncthreads per step.
// =====================================================================
__global__ void __launch_bounds__(256, 1) scan_kernel()
{
    __shared__ __align__(16) float stage[4][REC_];
    __shared__ float werr[2][8];

    const int b    = blockIdx.x;
    const int tid  = threadIdx.x;
    const int v    = tid >> 2;
    const int kg   = tid & 3;
    const int koff = kg * 16;
    const int lane = tid & 31;
    const int wrp  = tid >> 5;

    const float* base = g_inp + (size_t)b * S_ * REC_;
    float* yb = g_y + (size_t)b * S_ * DS_;

    #pragma unroll
    for (int t = 0; t < 3; t++) {
        cp_async8(&stage[t][2 * tid], base + (size_t)t * REC_ + 2 * tid);
        CP_COMMIT();
    }
    CP_WAIT2();
    __syncthreads();

    ull H[8];
    #pragma unroll
    for (int j = 0; j < 8; j++) H[j] = 0ull;

    for (int t = 0; t < S_; t++) {
        const float* st = stage[t & 3];

        ull q2[8], k2[8], a2[8], km2[8], qa2[8];
        #pragma unroll
        for (int j4 = 0; j4 < 4; j4++) {
            ulonglong2 t0 = *(const ulonglong2*)&st[0   + koff + 4 * j4];
            ulonglong2 t1 = *(const ulonglong2*)&st[64  + koff + 4 * j4];
            ulonglong2 t2 = *(const ulonglong2*)&st[128 + koff + 4 * j4];
            ulonglong2 t3 = *(const ulonglong2*)&st[192 + koff + 4 * j4];
            ulonglong2 t4 = *(const ulonglong2*)&st[256 + koff + 4 * j4];
            q2 [2*j4] = t0.x; q2 [2*j4+1] = t0.y;
            k2 [2*j4] = t1.x; k2 [2*j4+1] = t1.y;
            a2 [2*j4] = t2.x; a2 [2*j4+1] = t2.y;
            km2[2*j4] = t3.x; km2[2*j4+1] = t3.y;
            qa2[2*j4] = t4.x; qa2[2*j4+1] = t4.y;
        }
        float vt = st[320 + v];
        float c  = st[384];

        // three dots against H (packed over k)
        ull ap = 0ull, ak = 0ull, aq = 0ull;
        #pragma unroll
        for (int j = 0; j < 8; j++) {
            ap = fma2(q2[j],  H[j], ap);
            ak = fma2(k2[j],  H[j], ak);
            aq = fma2(qa2[j], H[j], aq);
        }
        float2 fp = unpack2(ap); float pred  = fp.x + fp.y;
        float2 fk = unpack2(ak); float kH    = fk.x + fk.y;
        float2 fq = unpack2(aq); float predA = fq.x + fq.y;

        pred  += __shfl_xor_sync(~0u, pred, 1);  pred  += __shfl_xor_sync(~0u, pred, 2);
        kH    += __shfl_xor_sync(~0u, kH, 1);    kH    += __shfl_xor_sync(~0u, kH, 2);
        predA += __shfl_xor_sync(~0u, predA, 1); predA += __shfl_xor_sync(~0u, predA, 2);

        // err = sum_v (v_t - pred)^2 : intra-warp over 8 v's, then cross-warp
        float d = vt - pred;
        float e = d * d;
        e += __shfl_xor_sync(~0u, e, 4);
        e += __shfl_xor_sync(~0u, e, 8);
        e += __shfl_xor_sync(~0u, e, 16);
        if (lane == 0) werr[t & 1][wrp] = e * 0.25f;  // each v counted 4x (kg copies)

        // prefetch step t+3
        if (t + 3 < S_)
            cp_async8(&stage[(t + 3) & 3][2 * tid],
                      base + (size_t)(t + 3) * REC_ + 2 * tid);
        CP_COMMIT();
        CP_WAIT2();
        __syncthreads();

        float errt = (werr[t & 1][0] + werr[t & 1][1]) + (werr[t & 1][2] + werr[t & 1][3])
                   + (werr[t & 1][4] + werr[t & 1][5]) + (werr[t & 1][6] + werr[t & 1][7]);
        float es = __expf(-errt * 0.99999899f);   // err / 1.000001
        float s  = 1.0f / (1.0f + es);
        float sd = s * (vt - kH);
        ull sd2 = pack2(sd, sd);

        #pragma unroll
        for (int j = 0; j < 8; j++)
            H[j] = fma2(a2[j], H[j], mul2(km2[j], sd2));

        if (kg == 0) yb[(size_t)t * DS_ + v] = predA + c * sd;
    }
}

// =====================================================================
// Kernel D: RMS-norm(y)*norm_w @ Wo^T  -> out[8192][2048]
// Tile 32 rows x 128 cols, 256 threads, Wo staged transposed in smem.
// =====================================================================
__global__ void __launch_bounds__(256) out_gemm(
    const float* __restrict__ norm_w, const float* __restrict__ Wo,
    float* __restrict__ out)
{
    __shared__ __align__(16) float ys[32 * 64];
    __shared__ __align__(16) float wos[64 * 128];   // [v][n]
    __shared__ float rs[32];
    __shared__ float nws[64];

    const int tid = threadIdx.x;
    const int m0 = blockIdx.y * 32;
    const int n0 = blockIdx.x * 128;

    for (int i = tid * 4; i < 2048; i += 1024)
        *(float4*)&ys[i] = *(const float4*)&g_y[(size_t)m0 * 64 + i];
    if (tid < 64) nws[tid] = norm_w[tid];
    {
        int n  = tid & 127;
        int vb = tid >> 7;
        #pragma unroll
        for (int q = 0; q < 8; q++) {
            int v4 = vb * 8 + q;
            float4 w = *(const float4*)&Wo[(size_t)(n0 + n) * 64 + v4 * 4];
            wos[(v4 * 4 + 0) * 128 + n] = w.x;
            wos[(v4 * 4 + 1) * 128 + n] = w.y;
            wos[(v4 * 4 + 2) * 128 + n] = w.z;
            wos[(v4 * 4 + 3) * 128 + n] = w.w;
        }
    }
    __syncthreads();

    {   // per-row rms: 8 lanes per row
        int r = tid >> 3, p = tid & 7;
        float sum = 0.0f;
        #pragma unroll
        for (int j = 0; j < 8; j++) { float x = ys[r * 64 + p * 8 + j]; sum += x * x; }
        sum += __shfl_xor_sync(~0u, sum, 1);
        sum += __shfl_xor_sync(~0u, sum, 2);
        sum += __shfl_xor_sync(~0u, sum, 4);
        if (p == 0) rs[r] = rsqrtf(sum * (1.0f / 64.0f) + 1e-6f);
    }
    __syncthreads();
    for (int i = tid; i < 2048; i += 256)
        ys[i] = ys[i] * rs[i >> 6] * nws[i & 63];
    __syncthreads();

    const int tn = tid & 31;   // n = n0 + tn + 32j
    const int tm = tid >> 5;   // rows m0 + tm*4 + i
    float acc[4][4];
    #pragma unroll
    for (int i = 0; i < 4; i++)
        #pragma unroll
        for (int j = 0; j < 4; j++) acc[i][j] = 0.0f;

    #pragma unroll 8
    for (int vv = 0; vv < 64; vv++) {
        float b0 = wos[vv * 128 + tn];
        float b1 = wos[vv * 128 + tn + 32];
        float b2 = wos[vv * 128 + tn + 64];
        float b3 = wos[vv * 128 + tn + 96];
        #pragma unroll
        for (int i = 0; i < 4; i++) {
            float a = ys[(tm * 4 + i) * 64 + vv];
            acc[i][0] += a * b0; acc[i][1] += a * b1;
            acc[i][2] += a * b2; acc[i][3] += a * b3;
        }
    }
    #pragma unroll
    for (int i = 0; i < 4; i++) {
        size_t row = (size_t)(m0 + tm * 4 + i) * 2048 + n0 + tn;
        #pragma unroll
        for (int j = 0; j < 4; j++) out[row + 32 * j] = acc[i][j];
    }
}

// =====================================================================
extern "C" void kernel_launch(void* const* d_in, const int* in_sizes, int n_in,
                              void* d_out, int out_size)
{
    const float* x      = (const float*)d_in[0];
    const float* Wk     = (const float*)d_in[1];
    const float* Wv     = (const float*)d_in[2];
    const float* Wq     = (const float*)d_in[3];
    const float* Wa_w   = (const float*)d_in[4];
    const float* Wa_b   = (const float*)d_in[5];
    const float* lam    = (const float*)d_in[6];
    const float* norm_w = (const float*)d_in[7];
    const float* Wo     = (const float*)d_in[8];
    float* out = (float*)d_out;

    proj_gemm<<<dim3(128, 4), 256>>>(x, Wk, Wv, Wq, Wa_w);
    prep_kernel<<<1024, 256>>>(Wa_b, lam);
    scan_kernel<<<4, 256>>>();
    out_gemm<<<dim3(16, 256), 256>>>(norm_w, Wo, out);
}

// round 2
// speedup vs baseline: 1.0230x; 1.0230x over previous
#include <cuda_runtime.h>
#include <cstdint>

typedef unsigned long long ull;

#define B_   4
#define S_   2048
#define DM_  2048
#define DS_  64
#define REC_ 336   // floats per (b,t) record: q k a km v | g h c pad

// ---------------- f32x2 packed helpers (Blackwell) ----------------
__device__ __forceinline__ ull fma2(ull a, ull b, ull c) {
    ull d; asm("fma.rn.f32x2 %0,%1,%2,%3;" : "=l"(d) : "l"(a), "l"(b), "l"(c)); return d;
}
__device__ __forceinline__ ull mul2(ull a, ull b) {
    ull d; asm("mul.rn.f32x2 %0,%1,%2;" : "=l"(d) : "l"(a), "l"(b)); return d;
}
__device__ __forceinline__ ull pack2(float lo, float hi) {
    ull d; asm("mov.b64 %0, {%1,%2};" : "=l"(d) : "f"(lo), "f"(hi)); return d;
}
__device__ __forceinline__ float2 unpack2(ull a) {
    float lo, hi; asm("mov.b64 {%0,%1}, %2;" : "=f"(lo), "=f"(hi) : "l"(a));
    return make_float2(lo, hi);
}

// ---------------- cp.async helpers ----------------
__device__ __forceinline__ void cp_async16(void* smem, const void* gmem) {
    uint32_t s = (uint32_t)__cvta_generic_to_shared(smem);
    asm volatile("cp.async.cg.shared.global [%0], [%1], 16;" :: "r"(s), "l"(gmem) : "memory");
}
#define CP_COMMIT()  asm volatile("cp.async.commit_group;" ::: "memory")
#define CP_WAIT3()   asm volatile("cp.async.wait_group 3;" ::: "memory")

// ---------------- scratch (device globals: no runtime alloc) ----------------
__device__ float g_raw[B_ * S_ * 256];   // [m][256]: k(0:64) v(64:128) q(128:192) r_pre(192:256)
__device__ float g_inp[B_ * S_ * REC_];  // record per token
__device__ float g_y  [B_ * S_ * DS_];   // scan output y

// =====================================================================
// Kernel A: projection GEMM.  g_raw[m][nt*64+n] = sum_k x[m][k]*W_nt[n][k]
// =====================================================================
#define BM 64
#define BN 64
#define BK 16

__global__ void __launch_bounds__(256) proj_gemm(
    const float* __restrict__ x,
    const float* __restrict__ Wk, const float* __restrict__ Wv,
    const float* __restrict__ Wq, const float* __restrict__ Wa)
{
    __shared__ __align__(16) float As[BK][BM + 2];
    __shared__ __align__(16) float Bs[BK][BN + 2];

    const int mt = blockIdx.x;
    const int nt = blockIdx.y;
    const float* W = (nt == 0) ? Wk : (nt == 1) ? Wv : (nt == 2) ? Wq : Wa;

    const int tid  = threadIdx.x;
    const int lrow = tid >> 2;
    const int lk   = (tid & 3) * 4;
    const float* xg = x + (size_t)(mt * BM + lrow) * DM_ + lk;
    const float* wg = W + (size_t)lrow * DM_ + lk;

    const int tn4 = (tid & 15) * 4;
    const int tm4 = (tid >> 4) * 4;

    ull acc[4][2];
    #pragma unroll
    for (int i = 0; i < 4; i++) { acc[i][0] = 0ull; acc[i][1] = 0ull; }

    float4 av = *(const float4*)xg;
    float4 bv = *(const float4*)wg;

    for (int k0 = 0; k0 < DM_; k0 += BK) {
        __syncthreads();
        As[lk + 0][lrow] = av.x; As[lk + 1][lrow] = av.y;
        As[lk + 2][lrow] = av.z; As[lk + 3][lrow] = av.w;
        Bs[lk + 0][lrow] = bv.x; Bs[lk + 1][lrow] = bv.y;
        Bs[lk + 2][lrow] = bv.z; Bs[lk + 3][lrow] = bv.w;
        float4 avn = av, bvn = bv;
        if (k0 + BK < DM_) {
            avn = *(const float4*)(xg + k0 + BK);
            bvn = *(const float4*)(wg + k0 + BK);
        }
        __syncthreads();
        #pragma unroll
        for (int kk = 0; kk < BK; kk++) {
            ull b0 = *(const ull*)&Bs[kk][tn4];
            ull b1 = *(const ull*)&Bs[kk][tn4 + 2];
            #pragma unroll
            for (int i = 0; i < 4; i++) {
                float a = As[kk][tm4 + i];
                ull pa = pack2(a, a);
                acc[i][0] = fma2(pa, b0, acc[i][0]);
                acc[i][1] = fma2(pa, b1, acc[i][1]);
            }
        }
        av = avn; bv = bvn;
    }

    #pragma unroll
    for (int i = 0; i < 4; i++) {
        int m = mt * BM + tm4 + i;
        #pragma unroll
        for (int j = 0; j < 2; j++) {
            float2 f = unpack2(acc[i][j]);
            *(float2*)&g_raw[(size_t)m * 256 + nt * 64 + tn4 + 2 * j] = f;
        }
    }
}

// =====================================================================
// Kernel B: per-token prep. One warp per token. Lane handles d and d+32.
// Record: [0]q [64]k [128]a [192]km=k*(1-a) [256]v [320]g [321]h [322]c
// (g,h filled by ghc_kernel; c = q·km written here)
// =====================================================================
__global__ void __launch_bounds__(256) prep_kernel(
    const float* __restrict__ Wa_b, const float* __restrict__ lam)
{
    const int g    = blockIdx.x * 8 + (threadIdx.x >> 5);
    const int lane = threadIdx.x & 31;
    const float* r_ = g_raw + (size_t)g * 256;

    float k0 = r_[lane],        k1 = r_[lane + 32];
    float v0 = r_[64 + lane],   v1 = r_[96 + lane];
    float q0 = r_[128 + lane],  q1 = r_[160 + lane];
    float z0 = r_[192 + lane] + Wa_b[lane];
    float z1 = r_[224 + lane] + Wa_b[lane + 32];

    float kn = k0 * k0 + k1 * k1;
    #pragma unroll
    for (int m = 1; m < 32; m <<= 1) kn += __shfl_xor_sync(~0u, kn, m);
    float kinv = 1.0f / fmaxf(sqrtf(kn), 1e-12f);
    k0 *= kinv; k1 *= kinv;

    float qn = q0 * q0 + q1 * q1;
    #pragma unroll
    for (int m = 1; m < 32; m <<= 1) qn += __shfl_xor_sync(~0u, qn, m);
    float qinv = 1.0f / fmaxf(sqrtf(qn), 1e-12f);
    q0 *= qinv; q1 *= qinv;

    float la0 = logf(1.0f / (1.0f + expf(-lam[lane])) + 1e-8f);
    float la1 = logf(1.0f / (1.0f + expf(-lam[lane + 32])) + 1e-8f);
    float rr0 = 1.0f / (1.0f + expf(-z0));
    float rr1 = 1.0f / (1.0f + expf(-z1));
    float al0 = expf(8.0f * rr0 * la0);
    float al1 = expf(8.0f * rr1 * la1);
    float km0 = k0 * (1.0f - al0), km1 = k1 * (1.0f - al1);

    float c = q0 * km0 + q1 * km1;
    #pragma unroll
    for (int m = 1; m < 32; m <<= 1) c += __shfl_xor_sync(~0u, c, m);

    float* o = g_inp + (size_t)g * REC_;
    o[lane] = q0;         o[lane + 32] = q1;
    o[64 + lane] = k0;    o[96 + lane] = k1;
    o[128 + lane] = al0;  o[160 + lane] = al1;
    o[192 + lane] = km0;  o[224 + lane] = km1;
    o[256 + lane] = v0;   o[288 + lane] = v1;
    if (lane == 0) o[322] = c;
}

// =====================================================================
// Kernel B2: cross-step scalar dots.  g_t = q_t·km_{t-1}, h_t = k_t·km_{t-1}
// One warp per token. t==0 (per batch) -> 0.
// =====================================================================
__global__ void __launch_bounds__(256) ghc_kernel()
{
    const int g    = blockIdx.x * 8 + (threadIdx.x >> 5);
    const int lane = threadIdx.x & 31;
    const int t    = g & (S_ - 1);
    float* cur = g_inp + (size_t)g * REC_;

    float gq = 0.0f, gh = 0.0f;
    if (t > 0) {
        const float* prev = cur - REC_;
        float q0 = cur[lane],      q1 = cur[lane + 32];
        float k0 = cur[64 + lane], k1 = cur[96 + lane];
        float m0 = prev[192 + lane], m1 = prev[224 + lane];
        gq = q0 * m0 + q1 * m1;
        gh = k0 * m0 + k1 * m1;
    }
    #pragma unroll
    for (int m = 1; m < 32; m <<= 1) {
        gq += __shfl_xor_sync(~0u, gq, m);
        gh += __shfl_xor_sync(~0u, gh, m);
    }
    if (lane == 0) { cur[320] = gq; cur[321] = gh; }
}

// =====================================================================
// Kernel C: sequential scan with deferred scalar recurrence.
// 4 CTAs (one per batch), 256 threads. Thread (v=tid>>2, kg=tid&3) owns
// H[kg*16..kg*16+15][v] as 8 f32x2. Only cross-step serial dep: s_{t-1}->s_t.
// =====================================================================
__global__ void __launch_bounds__(256, 1) scan_kernel()
{
    __shared__ __align__(16) float stage[8][REC_];
    __shared__ float4 part[2][8];

    const int b    = blockIdx.x;
    const int tid  = threadIdx.x;
    const int v    = tid >> 2;
    const int kg   = tid & 3;
    const int koff = kg * 16;
    const int lane = tid & 31;
    const int wrp  = tid >> 5;

    const float* base = g_inp + (size_t)b * S_ * REC_;
    float* yb = g_y + (size_t)b * S_ * DS_;

    #pragma unroll
    for (int t = 0; t < 5; t++) {
        if (tid < 84) cp_async16(&stage[t][tid * 4], base + (size_t)t * REC_ + tid * 4);
        CP_COMMIT();
    }
    CP_WAIT3();          // records 0,1 complete
    __syncthreads();

    ull H[8], Ha[8], kmp[8];
    #pragma unroll
    for (int j = 0; j < 8; j++) { H[j] = 0ull; Ha[j] = 0ull; kmp[j] = 0ull; }
    float s_prev = 0.0f, w_prev = 0.0f, C_cur = 0.0f;
    float v_cur = stage[0][256 + v];

    {   // prologue partials for step 0: A_0 = 0, w_{-1} = 0
        float u  = v_cur;
        float pp = u * u;
        pp += __shfl_xor_sync(~0u, pp, 4);
        pp += __shfl_xor_sync(~0u, pp, 8);
        pp += __shfl_xor_sync(~0u, pp, 16);
        if (lane == 0) part[0][wrp] = make_float4(pp, 0.0f, 0.0f, 0.0f);
    }
    __syncthreads();

    for (int i = 0; i < S_; i++) {
        const float* rc = stage[i & 7];
        const float* rn = stage[(i + 1) & 7];

        if (tid < 84 && i + 5 < S_)
            cp_async16(&stage[(i + 5) & 7][tid * 4],
                       base + (size_t)(i + 5) * REC_ + tid * 4);
        CP_COMMIT();
        CP_WAIT3();

        // ---- scalar phase: err_i, s_i (only serial chain) ----
        float4 p0 = part[i & 1][0], p1 = part[i & 1][1];
        float4 p2 = part[i & 1][2], p3 = part[i & 1][3];
        float4 p4 = part[i & 1][4], p5 = part[i & 1][5];
        float4 p6 = part[i & 1][6], p7 = part[i & 1][7];
        float P = ((p0.x + p1.x) + (p2.x + p3.x)) + ((p4.x + p5.x) + (p6.x + p7.x));
        float Q = ((p0.y + p1.y) + (p2.y + p3.y)) + ((p4.y + p5.y) + (p6.y + p7.y));
        float R = ((p0.z + p1.z) + (p2.z + p3.z)) + ((p4.z + p5.z) + (p6.z + p7.z));
        float gsc = rc[320], hsc = rc[321], csc = rc[322];
        float sg  = s_prev * gsc;
        float err = P - 2.0f * sg * Q + sg * sg * R;
        float es  = __expf(-err * 0.99999899f);
        float s   = __fdividef(1.0f, 1.0f + es);

        // w_i = v_i - k_i·H_{i-1} = (v_i - C_i) - s_{i-1} h_i w_{i-1}
        float w = (v_cur - C_cur) - s_prev * hsc * w_prev;

        // ---- materialize H_{i-1} = Ha(prev) + s_{i-1} w_{i-1} * km_{i-1} ----
        float sw = s_prev * w_prev;
        ull sw2 = pack2(sw, sw);
        #pragma unroll
        for (int j = 0; j < 8; j++) H[j] = fma2(kmp[j], sw2, Ha[j]);

        // ---- Ha = a_i ⊙ H_{i-1} ----
        #pragma unroll
        for (int j4 = 0; j4 < 4; j4++) {
            ulonglong2 aa = *(const ulonglong2*)&rc[128 + koff + 4 * j4];
            Ha[2 * j4]     = mul2(aa.x, H[2 * j4]);
            Ha[2 * j4 + 1] = mul2(aa.y, H[2 * j4 + 1]);
        }

        // ---- y_i = q_i·Ha + c_i s_i w_i ----
        ull yacc = 0ull;
        #pragma unroll
        for (int j4 = 0; j4 < 4; j4++) {
            ulonglong2 qq2 = *(const ulonglong2*)&rc[koff + 4 * j4];
            yacc = fma2(qq2.x, Ha[2 * j4], yacc);
            yacc = fma2(qq2.y, Ha[2 * j4 + 1], yacc);
        }
        float2 yf = unpack2(yacc);
        float yv = yf.x + yf.y;
        yv += __shfl_xor_sync(~0u, yv, 1);
        yv += __shfl_xor_sync(~0u, yv, 2);
        if (kg == 0) yb[(size_t)i * DS_ + v] = yv + csc * s * w;

        // ---- km_i -> regs (used to materialize H_i next iter) ----
        #pragma unroll
        for (int j4 = 0; j4 < 4; j4++) {
            ulonglong2 km2 = *(const ulonglong2*)&rc[192 + koff + 4 * j4];
            kmp[2 * j4]     = km2.x;
            kmp[2 * j4 + 1] = km2.y;
        }

        // ---- A_{i+1} = q_{i+1}·Ha, C_{i+1} = k_{i+1}·Ha ----
        ull accA = 0ull, accC = 0ull;
        #pragma unroll
        for (int j4 = 0; j4 < 4; j4++) {
            ulonglong2 qn2 = *(const ulonglong2*)&rn[koff + 4 * j4];
            ulonglong2 kn2 = *(const ulonglong2*)&rn[64 + koff + 4 * j4];
            accA = fma2(qn2.x, Ha[2 * j4], accA);
            accA = fma2(qn2.y, Ha[2 * j4 + 1], accA);
            accC = fma2(kn2.x, Ha[2 * j4], accC);
            accC = fma2(kn2.y, Ha[2 * j4 + 1], accC);
        }
        float2 fa = unpack2(accA); float Af = fa.x + fa.y;
        float2 fc = unpack2(accC); float Cf = fc.x + fc.y;
        Af += __shfl_xor_sync(~0u, Af, 1); Af += __shfl_xor_sync(~0u, Af, 2);
        Cf += __shfl_xor_sync(~0u, Cf, 1); Cf += __shfl_xor_sync(~0u, Cf, 2);

        // ---- partials for step i+1: P,Q̃,R̃ (s-independent) ----
        float vn = rn[256 + v];
        float u  = vn - Af;
        float pp = u * u, qq = u * w, rr = w * w;
        pp += __shfl_xor_sync(~0u, pp, 4);
        qq += __shfl_xor_sync(~0u, qq, 4);
        rr += __shfl_xor_sync(~0u, rr, 4);
        pp += __shfl_xor_sync(~0u, pp, 8);
        qq += __shfl_xor_sync(~0u, qq, 8);
        rr += __shfl_xor_sync(~0u, rr, 8);
        pp += __shfl_xor_sync(~0u, pp, 16);
        qq += __shfl_xor_sync(~0u, qq, 16);
        rr += __shfl_xor_sync(~0u, rr, 16);
        if (lane == 0) part[(i + 1) & 1][wrp] = make_float4(pp, qq, rr, 0.0f);

        s_prev = s; w_prev = w; C_cur = Cf; v_cur = vn;
        __syncthreads();
    }
}

// =====================================================================
// Kernel D: RMS-norm(y)*norm_w @ Wo^T  -> out[8192][2048]
// =====================================================================
__global__ void __launch_bounds__(256) out_gemm(
    const float* __restrict__ norm_w, const float* __restrict__ Wo,
    float* __restrict__ out)
{
    __shared__ __align__(16) float ys[32 * 64];
    __shared__ __align__(16) float wos[64 * 128];   // [v][n]
    __shared__ float rs[32];
    __shared__ float nws[64];

    const int tid = threadIdx.x;
    const int m0 = blockIdx.y * 32;
    const int n0 = blockIdx.x * 128;

    for (int i = tid * 4; i < 2048; i += 1024)
        *(float4*)&ys[i] = *(const float4*)&g_y[(size_t)m0 * 64 + i];
    if (tid < 64) nws[tid] = norm_w[tid];
    {
        int n  = tid & 127;
        int vb = tid >> 7;
        #pragma unroll
        for (int q = 0; q < 8; q++) {
            int v4 = vb * 8 + q;
            float4 w = *(const float4*)&Wo[(size_t)(n0 + n) * 64 + v4 * 4];
            wos[(v4 * 4 + 0) * 128 + n] = w.x;
            wos[(v4 * 4 + 1) * 128 + n] = w.y;
            wos[(v4 * 4 + 2) * 128 + n] = w.z;
            wos[(v4 * 4 + 3) * 128 + n] = w.w;
        }
    }
    __syncthreads();

    {
        int r = tid >> 3, p = tid & 7;
        float sum = 0.0f;
        #pragma unroll
        for (int j = 0; j < 8; j++) { float x = ys[r * 64 + p * 8 + j]; sum += x * x; }
        sum += __shfl_xor_sync(~0u, sum, 1);
        sum += __shfl_xor_sync(~0u, sum, 2);
        sum += __shfl_xor_sync(~0u, sum, 4);
        if (p == 0) rs[r] = rsqrtf(sum * (1.0f / 64.0f) + 1e-6f);
    }
    __syncthreads();
    for (int i = tid; i < 2048; i += 256)
        ys[i] = ys[i] * rs[i >> 6] * nws[i & 63];
    __syncthreads();

    const int tn = tid & 31;
    const int tm = tid >> 5;
    float acc[4][4];
    #pragma unroll
    for (int i = 0; i < 4; i++)
        #pragma unroll
        for (int j = 0; j < 4; j++) acc[i][j] = 0.0f;

    #pragma unroll 8
    for (int vv = 0; vv < 64; vv++) {
        float b0 = wos[vv * 128 + tn];
        float b1 = wos[vv * 128 + tn + 32];
        float b2 = wos[vv * 128 + tn + 64];
        float b3 = wos[vv * 128 + tn + 96];
        #pragma unroll
        for (int i = 0; i < 4; i++) {
            float a = ys[(tm * 4 + i) * 64 + vv];
            acc[i][0] += a * b0; acc[i][1] += a * b1;
            acc[i][2] += a * b2; acc[i][3] += a * b3;
        }
    }
    #pragma unroll
    for (int i = 0; i < 4; i++) {
        size_t row = (size_t)(m0 + tm * 4 + i) * 2048 + n0 + tn;
        #pragma unroll
        for (int j = 0; j < 4; j++) out[row + 32 * j] = acc[i][j];
    }
}

// =====================================================================
extern "C" void kernel_launch(void* const* d_in, const int* in_sizes, int n_in,
                              void* d_out, int out_size)
{
    const float* x      = (const float*)d_in[0];
    const float* Wk     = (const float*)d_in[1];
    const float* Wv     = (const float*)d_in[2];
    const float* Wq     = (const float*)d_in[3];
    const float* Wa_w   = (const float*)d_in[4];
    const float* Wa_b   = (const float*)d_in[5];
    const float* lam    = (const float*)d_in[6];
    const float* norm_w = (const float*)d_in[7];
    const float* Wo     = (const float*)d_in[8];
    float* out = (float*)d_out;

    proj_gemm<<<dim3(128, 4), 256>>>(x, Wk, Wv, Wq, Wa_w);
    prep_kernel<<<1024, 256>>>(Wa_b, lam);
    ghc_kernel<<<1024, 256>>>();
    scan_kernel<<<4, 256>>>();
    out_gemm<<<dim3(16, 256), 256>>>(norm_w, Wo, out);
}